// round 4
// baseline (speedup 1.0000x reference)
#include <cuda_runtime.h>
#include <math.h>

#define BB 8
#define CH 16

// Intermediate layouts:
// L1[b][kyi][kt][c][ix]  (F1 out, F2 in)   8*24*12*16*64 float2
// L2[b][ix][o][kyi][kt]  (F2 out, F3 in)   8*64*16*24*12 float2
__device__ float2 g_L1[BB*24*12*CH*64];
__device__ float2 g_L2[BB*64*CH*24*12];

// ---------------------------------------------------------------------------
// F1: fused t-DFT (64->12, real, even/odd paired) + y-DFT (64->24, E/O +
// mode-pair shared). Block = (b,c,ix), 288 threads.
// ---------------------------------------------------------------------------
__global__ void f1_fwd(const float* __restrict__ x) {
    __shared__ float  xs[64][65];
    __shared__ float2 twa[33][13];          // (cos, sin)(k*t'*2pi/64), k<=12, t'<=32
    __shared__ float2 G[64][12];            // t-DFT result [y][kt]
    __shared__ float2 E[32][12], O[32][12]; // y-pair sums/diffs (rows 1..31 used)
    int tid = threadIdx.x;  // 288

    for (int e = tid; e < 33*13; e += 288) {
        int tp = e / 13, k = e % 13;
        float sn, cs; sincospif((float)((tp*k) & 63) / 32.0f, &sn, &cs);
        twa[tp][k] = make_float2(cs, sn);
    }
    int bc = blockIdx.x >> 6, ix = blockIdx.x & 63;
    const float4* xv = (const float4*)(x + ((long)bc * 64 + ix) * 4096);
    for (int e = tid; e < 1024; e += 288) {
        float4 v = xv[e];
        int row = e >> 4, col = (e & 15) << 2;
        xs[row][col] = v.x; xs[row][col+1] = v.y; xs[row][col+2] = v.z; xs[row][col+3] = v.w;
    }
    __syncthreads();

    // stage A: t-DFT with pairing. thread = (y, group of 3 modes)
    if (tid < 256) {
        int y = tid >> 2, g = tid & 3;
        int k0 = 3 * g;
        float x0 = xs[y][0], x32 = xs[y][32];
        float re[3], im[3];
        #pragma unroll
        for (int j = 0; j < 3; j++) {
            float sgn = ((k0 + j) & 1) ? -1.0f : 1.0f;
            re[j] = x0 + sgn * x32;
            im[j] = 0.0f;
        }
        #pragma unroll 4
        for (int tp = 1; tp < 32; tp++) {
            float a = xs[y][tp], b2 = xs[y][64 - tp];
            float ee = a + b2, oo = a - b2;
            #pragma unroll
            for (int j = 0; j < 3; j++) {
                float2 w = twa[tp][k0 + j];
                re[j] = fmaf(ee, w.x, re[j]);
                im[j] = fmaf(-oo, w.y, im[j]);
            }
        }
        #pragma unroll
        for (int j = 0; j < 3; j++) G[y][k0 + j] = make_float2(re[j], im[j]);
    }
    __syncthreads();

    // E/O precompute over y-pairs
    for (int e = tid; e < 31 * 12; e += 288) {
        int yp = e / 12 + 1, kt = e % 12;
        float2 a = G[yp][kt], b2 = G[64 - yp][kt];
        E[yp][kt] = make_float2(a.x + b2.x, a.y + b2.y);
        O[yp][kt] = make_float2(a.x - b2.x, a.y - b2.y);
    }
    __syncthreads();

    // stage B: y-DFT, thread = (kp 0..12, kt 0..11); each computes modes kp and 64-kp
    if (tid < 156) {
        int kp = tid / 12, kt = tid % 12;
        float sgn = (kp & 1) ? -1.0f : 1.0f;
        float2 g0 = G[0][kt], g32 = G[32][kt];
        float rl = g0.x + sgn * g32.x, il = g0.y + sgn * g32.y;
        float rh = rl, ih = il;
        #pragma unroll 4
        for (int yp = 1; yp < 32; yp++) {
            float2 Ev = E[yp][kt], Ov = O[yp][kt];
            float2 w = twa[yp][kp];
            rl = fmaf(Ev.x, w.x, fmaf( Ov.y, w.y, rl));
            il = fmaf(Ev.y, w.x, fmaf(-Ov.x, w.y, il));
            rh = fmaf(Ev.x, w.x, fmaf(-Ov.y, w.y, rh));
            ih = fmaf(Ev.y, w.x, fmaf( Ov.x, w.y, ih));
        }
        int b = bc >> 4, c = bc & 15;
        if (kp < 12)   // low mode: kyi = kp
            g_L1[((((long)b*24 + kp)*12 + kt)*16 + c)*64 + ix] = make_float2(rl, il);
        if (kp >= 1)   // high mode 64-kp -> kyi = 24-kp
            g_L1[((((long)b*24 + (24 - kp))*12 + kt)*16 + c)*64 + ix] = make_float2(rh, ih);
    }
}

// ---------------------------------------------------------------------------
// F2: fused x-DFT + channel mix + inverse x-DFT. Block = (b,kyi,kt), 384 thr.
// ---------------------------------------------------------------------------
__global__ void f2_mix(const float* __restrict__ w1, const float* __restrict__ w2,
                       const float* __restrict__ w3, const float* __restrict__ w4) {
    __shared__ float2 sin_[16 * 64];   // in[c][ix]
    __shared__ float2 ws[24 * 256];    // ws[kxi][i*16+o]
    __shared__ float2 XF[16 * 24];     // [c][kxi]
    __shared__ float2 OF[16 * 24];     // [o][kxi]
    __shared__ float2 tw[64];
    int tid = threadIdx.x;  // 384
    if (tid < 64) {
        float sn, cs; sincospif((float)tid / 32.0f, &sn, &cs);
        tw[tid] = make_float2(cs, sn);
    }
    int bid = blockIdx.x;                    // (b*24+kyi)*12+kt
    int kt = bid % 12, kyi = (bid / 12) % 24, b = bid / 288;
    int kyp = kyi % 12;
    const float* wlo = (kyi < 12) ? w1 : w3;
    const float* whi = (kyi < 12) ? w2 : w4;

    {
        const float4* src = (const float4*)&g_L1[(long)bid * 1024];
        float4* dst = (float4*)sin_;
        for (int e = tid; e < 512; e += 384) dst[e] = src[e];
    }
    for (int e = tid; e < 6144; e += 384) {
        int kxi = e >> 8, r = e & 255;       // r = i*16+o
        int kxp = (kxi < 12) ? kxi : kxi - 12;
        const float* wp = (kxi < 12) ? wlo : whi;
        long gi = (((long)r * 12 + kxp) * 12 + kyp) * 12 + kt;
        ws[kxi * 256 + r] = ((const float2*)wp)[gi];
    }
    __syncthreads();

    // phase A: forward x-DFT. thread = (c, kxi)
    {
        int c = tid / 24, kxi = tid % 24;
        int kx = (kxi < 12) ? kxi : kxi + 40;
        float re = 0.f, im = 0.f;
        int idx = 0;
        #pragma unroll 8
        for (int ixx = 0; ixx < 64; ixx++) {
            float2 v = sin_[c * 64 + ixx];
            float2 w = tw[idx];
            re = fmaf(v.x, w.x, fmaf( v.y, w.y, re));
            im = fmaf(v.y, w.x, fmaf(-v.x, w.y, im));
            idx = (idx + kx) & 63;
        }
        XF[c * 24 + kxi] = make_float2(re, im);
    }
    __syncthreads();

    // phase B: 16x16 complex channel mix. thread = (kxi, o)
    {
        int kxi = tid >> 4, o = tid & 15;
        float re = 0.f, im = 0.f;
        #pragma unroll
        for (int i = 0; i < 16; i++) {
            float2 a  = XF[i * 24 + kxi];
            float2 wv = ws[kxi * 256 + i * 16 + o];
            re = fmaf(a.x, wv.x, fmaf(-a.y, wv.y, re));
            im = fmaf(a.x, wv.y, fmaf( a.y, wv.x, im));
        }
        OF[o * 24 + kxi] = make_float2(re, im);
    }
    __syncthreads();

    // phase C: inverse x-DFT (24 modes -> 64 ix)
    for (int e = tid; e < 1024; e += 384) {
        int o = e >> 6, ixx = e & 63;
        float re = 0.f, im = 0.f;
        #pragma unroll
        for (int kxi = 0; kxi < 24; kxi++) {
            int kx = (kxi < 12) ? kxi : kxi + 40;
            float2 v = OF[o * 24 + kxi];
            float2 w = tw[(kx * ixx) & 63];
            re = fmaf(v.x, w.x, fmaf(-v.y, w.y, re));
            im = fmaf(v.x, w.y, fmaf( v.y, w.x, im));
        }
        g_L2[((((long)b * 64 + ixx) * 16 + o) * 24 + kyi) * 12 + kt] = make_float2(re, im);
    }
}

// ---------------------------------------------------------------------------
// F3: fused inverse y-DFT + inverse real t-DFT (t/t+32 parity paired) +
// ReLU + 16x16 channel mix + bias. Block = (b,ix), 512 threads.
// ---------------------------------------------------------------------------
__global__ void f3_inv(const float* __restrict__ lo_w, const float* __restrict__ lo_b,
                       float* __restrict__ out) {
    __shared__ float2 Fin[16 * 288];     // [o][kyi*12+kt]
    __shared__ float2 H[16][16][12];     // [o][iyl][kt]
    __shared__ float  lwT[16][16];       // [c][o]
    __shared__ float  lb[16];
    __shared__ float2 tw[64];
    int tid = threadIdx.x;  // 512
    if (tid < 64) {
        float sn, cs; sincospif((float)tid / 32.0f, &sn, &cs);
        tw[tid] = make_float2(cs, sn);
    }
    if (tid < 256) lwT[tid & 15][tid >> 4] = lo_w[tid];   // lo_w[o][c] -> lwT[c][o]
    if (tid < 16)  lb[tid] = lo_b[tid];

    int b = blockIdx.x >> 6, ixx = blockIdx.x & 63;
    {
        const float4* src = (const float4*)&g_L2[((long)b * 64 + ixx) * 16 * 288];
        float4* dst = (float4*)Fin;
        for (int e = tid; e < 2304; e += 512) dst[e] = src[e];
    }
    __syncthreads();

    int iyl = tid >> 5, tp = tid & 31;
    // twiddles for t1 = tp (t2 = tp+32 handled by parity split)
    float c2[12], s2[12];
    #pragma unroll
    for (int k = 1; k < 12; k++) {
        float2 w = tw[(k * tp) & 63];
        c2[k] = 2.0f * w.x;
        s2[k] = 2.0f * w.y;
    }
    const float scale = 1.0f / (64.0f * 64.0f * 64.0f);

    for (int cy = 0; cy < 4; cy++) {
        // phase A: inverse y-DFT for 16 iy
        #pragma unroll
        for (int j = 0; j < 6; j++) {
            int e = tid + j * 512;                // 3072 outputs
            int o = e / 192, rem = e % 192;
            int iyA = cy * 16 + rem / 12, ktA = rem % 12;
            float re = 0.f, im = 0.f;
            #pragma unroll
            for (int kyi = 0; kyi < 24; kyi++) {
                int ky = (kyi < 12) ? kyi : kyi + 40;
                float2 v = Fin[o * 288 + kyi * 12 + ktA];
                float2 w = tw[(ky * iyA) & 63];
                re = fmaf(v.x, w.x, fmaf(-v.y, w.y, re));
                im = fmaf(v.x, w.y, fmaf( v.y, w.x, im));
            }
            H[o][rem / 12][ktA] = make_float2(re, im);
        }
        __syncthreads();

        // phase B: t-inverse (parity paired) + relu + mix
        float acc1[16], acc2[16];
        #pragma unroll
        for (int o = 0; o < 16; o++) { acc1[o] = lb[o]; acc2[o] = lb[o]; }

        #pragma unroll 4
        for (int c = 0; c < 16; c++) {
            const float4* Fp = (const float4*)&H[c][iyl][0];
            float4 a0 = Fp[0], a1 = Fp[1], a2 = Fp[2], a3 = Fp[3], a4 = Fp[4], a5 = Fp[5];
            // even-k and odd-k partial sums of 2*(Fr*cos - Fi*sin)
            float po = fmaf(a0.z, c2[1],  -a0.w * s2[1]);          // k=1
            float pe = fmaf(a1.x, c2[2],  -a1.y * s2[2]);          // k=2
            po = fmaf(a1.z, c2[3],  fmaf(-a1.w, s2[3],  po));
            pe = fmaf(a2.x, c2[4],  fmaf(-a2.y, s2[4],  pe));
            po = fmaf(a2.z, c2[5],  fmaf(-a2.w, s2[5],  po));
            pe = fmaf(a3.x, c2[6],  fmaf(-a3.y, s2[6],  pe));
            po = fmaf(a3.z, c2[7],  fmaf(-a3.w, s2[7],  po));
            pe = fmaf(a4.x, c2[8],  fmaf(-a4.y, s2[8],  pe));
            po = fmaf(a4.z, c2[9],  fmaf(-a4.w, s2[9],  po));
            pe = fmaf(a5.x, c2[10], fmaf(-a5.y, s2[10], pe));
            po = fmaf(a5.z, c2[11], fmaf(-a5.w, s2[11], po));
            float base = a0.x + pe;                 // F0 + even part
            float v1 = fmaxf((base + po) * scale, 0.0f);   // t = tp
            float v2 = fmaxf((base - po) * scale, 0.0f);   // t = tp+32
            const float4* lp = (const float4*)&lwT[c][0];
            float4 l0 = lp[0], l1 = lp[1], l2 = lp[2], l3 = lp[3];
            acc1[0]  = fmaf(l0.x, v1, acc1[0]);  acc2[0]  = fmaf(l0.x, v2, acc2[0]);
            acc1[1]  = fmaf(l0.y, v1, acc1[1]);  acc2[1]  = fmaf(l0.y, v2, acc2[1]);
            acc1[2]  = fmaf(l0.z, v1, acc1[2]);  acc2[2]  = fmaf(l0.z, v2, acc2[2]);
            acc1[3]  = fmaf(l0.w, v1, acc1[3]);  acc2[3]  = fmaf(l0.w, v2, acc2[3]);
            acc1[4]  = fmaf(l1.x, v1, acc1[4]);  acc2[4]  = fmaf(l1.x, v2, acc2[4]);
            acc1[5]  = fmaf(l1.y, v1, acc1[5]);  acc2[5]  = fmaf(l1.y, v2, acc2[5]);
            acc1[6]  = fmaf(l1.z, v1, acc1[6]);  acc2[6]  = fmaf(l1.z, v2, acc2[6]);
            acc1[7]  = fmaf(l1.w, v1, acc1[7]);  acc2[7]  = fmaf(l1.w, v2, acc2[7]);
            acc1[8]  = fmaf(l2.x, v1, acc1[8]);  acc2[8]  = fmaf(l2.x, v2, acc2[8]);
            acc1[9]  = fmaf(l2.y, v1, acc1[9]);  acc2[9]  = fmaf(l2.y, v2, acc2[9]);
            acc1[10] = fmaf(l2.z, v1, acc1[10]); acc2[10] = fmaf(l2.z, v2, acc2[10]);
            acc1[11] = fmaf(l2.w, v1, acc1[11]); acc2[11] = fmaf(l2.w, v2, acc2[11]);
            acc1[12] = fmaf(l3.x, v1, acc1[12]); acc2[12] = fmaf(l3.x, v2, acc2[12]);
            acc1[13] = fmaf(l3.y, v1, acc1[13]); acc2[13] = fmaf(l3.y, v2, acc2[13]);
            acc1[14] = fmaf(l3.z, v1, acc1[14]); acc2[14] = fmaf(l3.z, v2, acc2[14]);
            acc1[15] = fmaf(l3.w, v1, acc1[15]); acc2[15] = fmaf(l3.w, v2, acc2[15]);
        }
        int iy = cy * 16 + iyl;
        long obase = (long)b * 16 * 262144 + (long)ixx * 4096 + (long)iy * 64;
        #pragma unroll
        for (int o = 0; o < 16; o++) {
            out[obase + (long)o * 262144 + tp]      = acc1[o];
            out[obase + (long)o * 262144 + tp + 32] = acc2[o];
        }
        __syncthreads();   // protect H before next chunk
    }
}

// ---------------------------------------------------------------------------
extern "C" void kernel_launch(void* const* d_in, const int* in_sizes, int n_in,
                              void* d_out, int out_size) {
    const float* x    = (const float*)d_in[0];
    const float* w1   = (const float*)d_in[1];
    const float* w2   = (const float*)d_in[2];
    const float* w3   = (const float*)d_in[3];
    const float* w4   = (const float*)d_in[4];
    const float* lo_w = (const float*)d_in[5];
    const float* lo_b = (const float*)d_in[6];
    float* out = (float*)d_out;

    f1_fwd<<<BB*CH*64, 288>>>(x);
    f2_mix<<<BB*24*12, 384>>>(w1, w2, w3, w4);
    f3_inv<<<BB*64, 512>>>(lo_w, lo_b, out);
}

// round 7
// speedup vs baseline: 1.4124x; 1.4124x over previous
#include <cuda_runtime.h>
#include <math.h>

#define BB 8
#define CH 16
#define NFREQ (24*24*12)   // 6912

// Scratch
__device__ float2 g_bufA[BB*CH*64*64*12];   // [bc][ix][iy][kt] fwd / [bo][ix][iy][kt] inv
__device__ float2 g_bufB[BB*CH*64*24*12];   // [bc or bo][ix][kyi][kt]
__device__ float2 g_XF2[NFREQ*128];         // [f][bc]
__device__ float2 g_OF2[NFREQ*128];         // [f][bc]
__device__ float2 g_WT[NFREQ*256];          // [f][i*16+o]

// ---------------------------------------------------------------------------
// KW: one-time weight transpose into frequency-major coalesced layout.
// ---------------------------------------------------------------------------
__global__ void kw_prep(const float* __restrict__ w1, const float* __restrict__ w2,
                        const float* __restrict__ w3, const float* __restrict__ w4) {
    int f = blockIdx.x;                     // kxi*288 + kyi*12 + kt
    int kxi = f / 288, kyi = (f / 12) % 24, kt = f % 12;
    const float* w = (kxi < 12) ? ((kyi < 12) ? w1 : w3)
                                : ((kyi < 12) ? w2 : w4);
    int kxp = kxi % 12, kyp = kyi % 12;
    int r = threadIdx.x;                    // 256 = i*16+o
    long gi = (long)r * 1728 + ((long)kxp * 12 + kyp) * 12 + kt;
    g_WT[(long)f * 256 + r] = ((const float2*)w)[gi];
}

// ---------------------------------------------------------------------------
// K1: real t-DFT 64 -> 12 modes with +32 parity pairing (2x FMA cut).
// 1 thread = 1 row. twm[tp][k]=(cos,sin)(2pi k tp/64).
// ---------------------------------------------------------------------------
__global__ void k1_fft_t(const float* __restrict__ x) {
    __shared__ float  xs[128][65];
    __shared__ float2 twm[32][12];
    int tid = threadIdx.x;  // 128
    for (int e = tid; e < 384; e += 128) {
        int tp = e / 12, k = e % 12;
        float sn, cs; sincospif((float)((tp * k) & 63) / 32.0f, &sn, &cs);
        twm[tp][k] = make_float2(cs, sn);
    }
    long base = (long)blockIdx.x * 128 * 64;
    const float4* xv = (const float4*)(x + base);
    for (int e = tid; e < 2048; e += 128) {
        float4 v = xv[e];
        int row = e >> 4, col = (e & 15) << 2;
        xs[row][col] = v.x; xs[row][col+1] = v.y; xs[row][col+2] = v.z; xs[row][col+3] = v.w;
    }
    __syncthreads();

    float re[12], im[12];
    #pragma unroll
    for (int k = 0; k < 12; k++) { re[k] = 0.f; im[k] = 0.f; }

    #pragma unroll 4
    for (int tp = 0; tp < 32; tp++) {
        float a = xs[tid][tp], b = xs[tid][tp + 32];
        float ve = a + b, vo = a - b;
        const float4* tp4 = (const float4*)&twm[tp][0];
        #pragma unroll
        for (int j = 0; j < 6; j++) {     // float4 = modes (2j even, 2j+1 odd)
            float4 w = tp4[j];
            re[2*j]   = fmaf(ve, w.x, re[2*j]);
            im[2*j]   = fmaf(-ve, w.y, im[2*j]);
            re[2*j+1] = fmaf(vo, w.z, re[2*j+1]);
            im[2*j+1] = fmaf(-vo, w.w, im[2*j+1]);
        }
    }
    float4* ob = (float4*)&g_bufA[((long)blockIdx.x * 128 + tid) * 12];
    #pragma unroll
    for (int j = 0; j < 6; j++)
        ob[j] = make_float4(re[2*j], im[2*j], re[2*j+1], im[2*j+1]);
}

// ---------------------------------------------------------------------------
// K2: complex y-DFT 64 -> 24 modes with +32 parity pairing.
// Block=(bc, 8 ix), 96 thr=(ixl,kt), 24 complex accums.
// ---------------------------------------------------------------------------
__global__ void k2_fft_y() {
    __shared__ float2 sIn[8][2][192];      // [ix][half][yy*12+kt], yy<16
    __shared__ float2 twy[32][24];         // (c,s) at (ky*yp)&63
    int tid = threadIdx.x;  // 96
    for (int e = tid; e < 768; e += 96) {
        int yp = e / 24, kyi = e % 24;
        int ky = (kyi < 12) ? kyi : kyi + 40;
        float sn, cs; sincospif((float)((ky * yp) & 63) / 32.0f, &sn, &cs);
        twy[yp][kyi] = make_float2(cs, sn);
    }
    int bc  = blockIdx.x >> 3;
    int ixg = (blockIdx.x & 7) * 8;
    int ixl = tid / 12, kt = tid % 12;

    float ar[24], ai[24];
    #pragma unroll
    for (int i = 0; i < 24; i++) { ar[i] = 0.f; ai[i] = 0.f; }

    for (int cy = 0; cy < 2; cy++) {
        __syncthreads();
        for (int e = tid; e < 1536; e += 96) {
            int il = e / 192, h = (e / 96) & 1, r = e % 96;
            const float4* src = (const float4*)&g_bufA[((long)(bc*64 + ixg + il) * 64 + cy*16 + h*32) * 12];
            ((float4*)&sIn[il][h][0])[r] = src[r];
        }
        __syncthreads();
        for (int yy = 0; yy < 16; yy++) {
            int yp = cy * 16 + yy;
            float2 v1 = sIn[ixl][0][yy * 12 + kt];
            float2 v2 = sIn[ixl][1][yy * 12 + kt];
            float vex = v1.x + v2.x, vey = v1.y + v2.y;
            float vox = v1.x - v2.x, voy = v1.y - v2.y;
            const float4* tp4 = (const float4*)&twy[yp][0];
            #pragma unroll
            for (int j = 0; j < 12; j++) {   // modes 2j (even ky), 2j+1 (odd ky)
                float4 w = tp4[j];
                ar[2*j]   = fmaf(vex, w.x, fmaf( vey, w.y, ar[2*j]));
                ai[2*j]   = fmaf(vey, w.x, fmaf(-vex, w.y, ai[2*j]));
                ar[2*j+1] = fmaf(vox, w.z, fmaf( voy, w.w, ar[2*j+1]));
                ai[2*j+1] = fmaf(voy, w.z, fmaf(-vox, w.w, ai[2*j+1]));
            }
        }
    }
    long obase = ((long)(bc * 64 + ixg + ixl) * 24) * 12 + kt;
    #pragma unroll
    for (int kyi = 0; kyi < 24; kyi++)
        g_bufB[obase + kyi * 12] = make_float2(ar[kyi], ai[kyi]);
}

// ---------------------------------------------------------------------------
// K3: complex x-DFT 64 -> 24 modes with +32 parity pairing.
// Block = bc, 288 thr = (kyi*12+kt), 24 kxi accums. Writes XF2[f][bc].
// ---------------------------------------------------------------------------
__global__ void k3_fft_x() {
    __shared__ float2 sIn[8][2][288];      // [xl][half][kyi*12+kt]
    __shared__ float2 twx[32][24];
    int tid = threadIdx.x;  // 288
    for (int e = tid; e < 768; e += 288) {
        int xp = e / 24, kxi = e % 24;
        int kx = (kxi < 12) ? kxi : kxi + 40;
        float sn, cs; sincospif((float)((kx * xp) & 63) / 32.0f, &sn, &cs);
        twx[xp][kxi] = make_float2(cs, sn);
    }
    int bc = blockIdx.x;

    float ar[24], ai[24];
    #pragma unroll
    for (int i = 0; i < 24; i++) { ar[i] = 0.f; ai[i] = 0.f; }

    for (int cx = 0; cx < 4; cx++) {
        __syncthreads();
        for (int e = tid; e < 2304; e += 288) {
            int xl = e / 288, h = (e / 144) & 1, r = e % 144;
            const float4* src = (const float4*)&g_bufB[((long)(bc * 64 + cx*8 + xl + h*32)) * 288];
            ((float4*)&sIn[xl][h][0])[r] = src[r];
        }
        __syncthreads();
        for (int xl = 0; xl < 8; xl++) {
            int xp = cx * 8 + xl;
            float2 v1 = sIn[xl][0][tid];
            float2 v2 = sIn[xl][1][tid];
            float vex = v1.x + v2.x, vey = v1.y + v2.y;
            float vox = v1.x - v2.x, voy = v1.y - v2.y;
            const float4* tp4 = (const float4*)&twx[xp][0];
            #pragma unroll
            for (int j = 0; j < 12; j++) {
                float4 w = tp4[j];
                ar[2*j]   = fmaf(vex, w.x, fmaf( vey, w.y, ar[2*j]));
                ai[2*j]   = fmaf(vey, w.x, fmaf(-vex, w.y, ai[2*j]));
                ar[2*j+1] = fmaf(vox, w.z, fmaf( voy, w.w, ar[2*j+1]));
                ai[2*j+1] = fmaf(voy, w.z, fmaf(-vox, w.w, ai[2*j+1]));
            }
        }
    }
    #pragma unroll
    for (int kxi = 0; kxi < 24; kxi++)
        g_XF2[(long)(kxi * 288 + tid) * 128 + bc] = make_float2(ar[kxi], ai[kxi]);
}

// ---------------------------------------------------------------------------
// K4: per-frequency 16x16 complex channel mix. 4 freqs/block, 512 threads.
// Coalesced weights via g_WT, coalesced data via XF2/OF2.
// ---------------------------------------------------------------------------
__global__ void k4_mix() {
    __shared__ float2 ws[4][256];
    __shared__ float2 xs[4][128];
    int tid  = threadIdx.x;            // 512
    int slot = tid >> 7, st = tid & 127;
    int f = blockIdx.x * 4 + slot;
    {
        const float4* wp = (const float4*)&g_WT[(long)f * 256];
        ((float4*)&ws[slot][0])[st] = wp[st];
    }
    xs[slot][st] = g_XF2[(long)f * 128 + st];
    __syncthreads();
    int b = st >> 4, o = st & 15;
    float re = 0.f, im = 0.f;
    #pragma unroll
    for (int i = 0; i < 16; i++) {
        float2 a  = xs[slot][b * 16 + i];
        float2 wv = ws[slot][i * 16 + o];
        re = fmaf(a.x, wv.x, fmaf(-a.y, wv.y, re));
        im = fmaf(a.x, wv.y, fmaf( a.y, wv.x, im));
    }
    g_OF2[(long)f * 128 + st] = make_float2(re, im);
}

// ---------------------------------------------------------------------------
// K5: inverse x-DFT 24 -> 64 with conjugate-mode pairing (S/D in smem).
// Block = (bo, 4 kyi), 256 thr = (kslot, ix).
// ---------------------------------------------------------------------------
__global__ void k5_ifft_x() {
    __shared__ float4 sSD[4][11][12];    // (Sx,Sy,Dx,Dy) pair kp=1..11
    __shared__ float2 sV0[4][12], sV12[4][12];
    __shared__ float2 tw[64];
    int tid = threadIdx.x;  // 256
    if (tid < 64) {
        float sn, cs; sincospif((float)tid / 32.0f, &sn, &cs);
        tw[tid] = make_float2(cs, sn);
    }
    int bo  = blockIdx.x / 6;
    int kyg = (blockIdx.x % 6) * 4;
    if (tid < 48) {
        int ks = tid / 12, kt = tid % 12;
        sV0[ks][kt]  = g_OF2[(long)(0 * 288 + (kyg + ks) * 12 + kt) * 128 + bo];
        sV12[ks][kt] = g_OF2[(long)(12 * 288 + (kyg + ks) * 12 + kt) * 128 + bo];
    }
    for (int e = tid; e < 528; e += 256) {
        int ks = e / 132, r = e % 132, kp = r / 12 + 1, kt = r % 12;
        float2 v1 = g_OF2[(long)(kp * 288 + (kyg + ks) * 12 + kt) * 128 + bo];
        float2 v2 = g_OF2[(long)((24 - kp) * 288 + (kyg + ks) * 12 + kt) * 128 + bo];
        sSD[ks][kp - 1][kt] = make_float4(v1.x + v2.x, v1.y + v2.y, v1.x - v2.x, v1.y - v2.y);
    }
    __syncthreads();
    int kslot = tid >> 6, ix = tid & 63;

    float ar[12], ai[12];
    {
        const float4* v0 = (const float4*)&sV0[kslot][0];
        #pragma unroll
        for (int j = 0; j < 6; j++) {
            float4 v = v0[j];
            ar[2*j] = v.x; ai[2*j] = v.y; ar[2*j+1] = v.z; ai[2*j+1] = v.w;
        }
    }
    #pragma unroll
    for (int kp = 1; kp < 12; kp++) {
        float2 w = tw[(kp * ix) & 63];
        #pragma unroll
        for (int kt = 0; kt < 12; kt++) {
            float4 sd = sSD[kslot][kp - 1][kt];
            ar[kt] = fmaf(sd.x, w.x, fmaf(-sd.w, w.y, ar[kt]));   // Sx*c - Dy*s
            ai[kt] = fmaf(sd.z, w.y, fmaf( sd.y, w.x, ai[kt]));   // Dx*s + Sy*c
        }
    }
    {   // single mode kx = 52
        float2 w = tw[(52 * ix) & 63];
        const float4* vp = (const float4*)&sV12[kslot][0];
        #pragma unroll
        for (int j = 0; j < 6; j++) {
            float4 v = vp[j];
            ar[2*j]   = fmaf(v.x, w.x, fmaf(-v.y, w.y, ar[2*j]));
            ai[2*j]   = fmaf(v.x, w.y, fmaf( v.y, w.x, ai[2*j]));
            ar[2*j+1] = fmaf(v.z, w.x, fmaf(-v.w, w.y, ar[2*j+1]));
            ai[2*j+1] = fmaf(v.z, w.y, fmaf( v.w, w.x, ai[2*j+1]));
        }
    }
    float4* ob = (float4*)&g_bufB[((long)(bo * 64 + ix) * 24 + kyg + kslot) * 12];
    #pragma unroll
    for (int j = 0; j < 6; j++)
        ob[j] = make_float4(ar[2*j], ai[2*j], ar[2*j+1], ai[2*j+1]);
}

// ---------------------------------------------------------------------------
// K6: inverse y-DFT 24 -> 64 with conjugate-mode pairing.
// Block = (bo, 4 ix), 256 thr = (ixslot, iy).
// ---------------------------------------------------------------------------
__global__ void k6_ifft_y() {
    __shared__ float4 sSD[4][11][12];
    __shared__ float2 sV0[4][12], sV12[4][12];
    __shared__ float2 tw[64];
    int tid = threadIdx.x;  // 256
    if (tid < 64) {
        float sn, cs; sincospif((float)tid / 32.0f, &sn, &cs);
        tw[tid] = make_float2(cs, sn);
    }
    int bo  = blockIdx.x >> 4;
    int ixg = (blockIdx.x & 15) * 4;
    if (tid < 48) {
        int is = tid / 12, kt = tid % 12;
        long rbase = ((long)(bo * 64 + ixg + is) * 24) * 12;
        sV0[is][kt]  = g_bufB[rbase + 0 * 12 + kt];
        sV12[is][kt] = g_bufB[rbase + 12 * 12 + kt];
    }
    for (int e = tid; e < 528; e += 256) {
        int is = e / 132, r = e % 132, kp = r / 12 + 1, kt = r % 12;
        long rbase = ((long)(bo * 64 + ixg + is) * 24) * 12;
        float2 v1 = g_bufB[rbase + kp * 12 + kt];
        float2 v2 = g_bufB[rbase + (24 - kp) * 12 + kt];
        sSD[is][kp - 1][kt] = make_float4(v1.x + v2.x, v1.y + v2.y, v1.x - v2.x, v1.y - v2.y);
    }
    __syncthreads();
    int islot = tid >> 6, iy = tid & 63;

    float ar[12], ai[12];
    {
        const float4* v0 = (const float4*)&sV0[islot][0];
        #pragma unroll
        for (int j = 0; j < 6; j++) {
            float4 v = v0[j];
            ar[2*j] = v.x; ai[2*j] = v.y; ar[2*j+1] = v.z; ai[2*j+1] = v.w;
        }
    }
    #pragma unroll
    for (int kp = 1; kp < 12; kp++) {
        float2 w = tw[(kp * iy) & 63];
        #pragma unroll
        for (int kt = 0; kt < 12; kt++) {
            float4 sd = sSD[islot][kp - 1][kt];
            ar[kt] = fmaf(sd.x, w.x, fmaf(-sd.w, w.y, ar[kt]));
            ai[kt] = fmaf(sd.z, w.y, fmaf( sd.y, w.x, ai[kt]));
        }
    }
    {   // single mode ky = 52
        float2 w = tw[(52 * iy) & 63];
        const float4* vp = (const float4*)&sV12[islot][0];
        #pragma unroll
        for (int j = 0; j < 6; j++) {
            float4 v = vp[j];
            ar[2*j]   = fmaf(v.x, w.x, fmaf(-v.y, w.y, ar[2*j]));
            ai[2*j]   = fmaf(v.x, w.y, fmaf( v.y, w.x, ai[2*j]));
            ar[2*j+1] = fmaf(v.z, w.x, fmaf(-v.w, w.y, ar[2*j+1]));
            ai[2*j+1] = fmaf(v.z, w.y, fmaf( v.w, w.x, ai[2*j+1]));
        }
    }
    float4* ob = (float4*)&g_bufA[((long)(bo * 64 + ixg + islot) * 64 + iy) * 12];
    #pragma unroll
    for (int j = 0; j < 6; j++)
        ob[j] = make_float4(ar[2*j], ai[2*j], ar[2*j+1], ai[2*j+1]);
}

// ---------------------------------------------------------------------------
// K7: inverse real t-DFT with t/t+32 parity split + ReLU + 16x16 mix + bias.
// Block = 8 xy-slots x 32 tp = 256 threads; warp == slot (broadcast LDS).
// ---------------------------------------------------------------------------
__global__ void k7_final(const float* __restrict__ lo_w,
                         const float* __restrict__ lo_b,
                         float* __restrict__ out) {
    __shared__ float2 F[8][16][12];
    __shared__ float  lwT[16][16];   // [c][o]
    __shared__ float  lb[16];
    __shared__ float2 tw[64];
    int tid = threadIdx.x;  // 256
    if (tid < 64) {
        float sn, cs; sincospif((float)tid / 32.0f, &sn, &cs);
        tw[tid] = make_float2(cs, sn);
    }
    lwT[tid & 15][tid >> 4] = lo_w[tid];
    if (tid < 16) lb[tid] = lo_b[tid];

    int b   = blockIdx.x >> 9;
    int xy0 = (blockIdx.x & 511) * 8;
    for (int e = tid; e < 768; e += 256) {
        int slot = e / 96, c = (e % 96) / 6, j = e % 6;
        const float4* src = (const float4*)g_bufA + ((long)(b * 16 + c) * 4096 + xy0 + slot) * 6 + j;
        ((float4*)&F[slot][c][0])[j] = *src;
    }
    __syncthreads();

    int slot = tid >> 5, tp = tid & 31;
    float c2[12], s2[12];
    #pragma unroll
    for (int k = 1; k < 12; k++) {
        float2 w = tw[(k * tp) & 63];
        c2[k] = 2.0f * w.x;
        s2[k] = 2.0f * w.y;
    }

    float acc1[16], acc2[16];
    #pragma unroll
    for (int o = 0; o < 16; o++) { acc1[o] = lb[o]; acc2[o] = lb[o]; }

    const float scale = 1.0f / (64.0f * 64.0f * 64.0f);
    #pragma unroll 4
    for (int c = 0; c < 16; c++) {
        const float4* Fp = (const float4*)&F[slot][c][0];
        float4 a0 = Fp[0], a1 = Fp[1], a2 = Fp[2], a3 = Fp[3], a4 = Fp[4], a5 = Fp[5];
        float po = fmaf(a0.z, c2[1],  -a0.w * s2[1]);
        float pe = fmaf(a1.x, c2[2],  -a1.y * s2[2]);
        po = fmaf(a1.z, c2[3],  fmaf(-a1.w, s2[3],  po));
        pe = fmaf(a2.x, c2[4],  fmaf(-a2.y, s2[4],  pe));
        po = fmaf(a2.z, c2[5],  fmaf(-a2.w, s2[5],  po));
        pe = fmaf(a3.x, c2[6],  fmaf(-a3.y, s2[6],  pe));
        po = fmaf(a3.z, c2[7],  fmaf(-a3.w, s2[7],  po));
        pe = fmaf(a4.x, c2[8],  fmaf(-a4.y, s2[8],  pe));
        po = fmaf(a4.z, c2[9],  fmaf(-a4.w, s2[9],  po));
        pe = fmaf(a5.x, c2[10], fmaf(-a5.y, s2[10], pe));
        po = fmaf(a5.z, c2[11], fmaf(-a5.w, s2[11], po));
        float base = a0.x + pe;
        float v1 = fmaxf((base + po) * scale, 0.0f);   // t = tp
        float v2 = fmaxf((base - po) * scale, 0.0f);   // t = tp+32
        const float4* lp = (const float4*)&lwT[c][0];
        float4 l0 = lp[0], l1 = lp[1], l2 = lp[2], l3 = lp[3];
        acc1[0]  = fmaf(l0.x, v1, acc1[0]);  acc2[0]  = fmaf(l0.x, v2, acc2[0]);
        acc1[1]  = fmaf(l0.y, v1, acc1[1]);  acc2[1]  = fmaf(l0.y, v2, acc2[1]);
        acc1[2]  = fmaf(l0.z, v1, acc1[2]);  acc2[2]  = fmaf(l0.z, v2, acc2[2]);
        acc1[3]  = fmaf(l0.w, v1, acc1[3]);  acc2[3]  = fmaf(l0.w, v2, acc2[3]);
        acc1[4]  = fmaf(l1.x, v1, acc1[4]);  acc2[4]  = fmaf(l1.x, v2, acc2[4]);
        acc1[5]  = fmaf(l1.y, v1, acc1[5]);  acc2[5]  = fmaf(l1.y, v2, acc2[5]);
        acc1[6]  = fmaf(l1.z, v1, acc1[6]);  acc2[6]  = fmaf(l1.z, v2, acc2[6]);
        acc1[7]  = fmaf(l1.w, v1, acc1[7]);  acc2[7]  = fmaf(l1.w, v2, acc2[7]);
        acc1[8]  = fmaf(l2.x, v1, acc1[8]);  acc2[8]  = fmaf(l2.x, v2, acc2[8]);
        acc1[9]  = fmaf(l2.y, v1, acc1[9]);  acc2[9]  = fmaf(l2.y, v2, acc2[9]);
        acc1[10] = fmaf(l2.z, v1, acc1[10]); acc2[10] = fmaf(l2.z, v2, acc2[10]);
        acc1[11] = fmaf(l2.w, v1, acc1[11]); acc2[11] = fmaf(l2.w, v2, acc2[11]);
        acc1[12] = fmaf(l3.x, v1, acc1[12]); acc2[12] = fmaf(l3.x, v2, acc2[12]);
        acc1[13] = fmaf(l3.y, v1, acc1[13]); acc2[13] = fmaf(l3.y, v2, acc2[13]);
        acc1[14] = fmaf(l3.z, v1, acc1[14]); acc2[14] = fmaf(l3.z, v2, acc2[14]);
        acc1[15] = fmaf(l3.w, v1, acc1[15]); acc2[15] = fmaf(l3.w, v2, acc2[15]);
    }

    long obase = (long)b * 16 * 262144 + (long)(xy0 + slot) * 64;
    #pragma unroll
    for (int o = 0; o < 16; o++) {
        out[obase + (long)o * 262144 + tp]      = acc1[o];
        out[obase + (long)o * 262144 + tp + 32] = acc2[o];
    }
}

// ---------------------------------------------------------------------------
extern "C" void kernel_launch(void* const* d_in, const int* in_sizes, int n_in,
                              void* d_out, int out_size) {
    const float* x    = (const float*)d_in[0];
    const float* w1   = (const float*)d_in[1];
    const float* w2   = (const float*)d_in[2];
    const float* w3   = (const float*)d_in[3];
    const float* w4   = (const float*)d_in[4];
    const float* lo_w = (const float*)d_in[5];
    const float* lo_b = (const float*)d_in[6];
    float* out = (float*)d_out;

    kw_prep<<<NFREQ, 256>>>(w1, w2, w3, w4);
    k1_fft_t<<<4096, 128>>>(x);
    k2_fft_y<<<1024, 96>>>();
    k3_fft_x<<<128, 288>>>();
    k4_mix<<<NFREQ/4, 512>>>();
    k5_ifft_x<<<768, 256>>>();
    k6_ifft_y<<<2048, 256>>>();
    k7_final<<<4096, 256>>>(lo_w, lo_b, out);
}